// round 1
// baseline (speedup 1.0000x reference)
#include <cuda_runtime.h>

#define BATCH 8
#define M 4096
#define NPTS 4096
#define RPW 8                      // rows per warp (register-blocked)
#define WARPS 8
#define ROWS_PER_BLOCK (RPW * WARPS)          // 64
#define BLOCKS_PER_BATCH (M / ROWS_PER_BLOCK) // 64
#define NBLOCKS (BATCH * BLOCKS_PER_BATCH)    // 512

// arg of exp2: exp(-d/0.1) = 2^(-d * 10 * log2(e))
#define NEG_K (-14.4269504088896340736f)

__device__ float g_row[BATCH * M];   // per-(b,m) weighted result (scratch)

__device__ __forceinline__ float fast_sqrt(float x) {
    float r; asm("sqrt.approx.f32 %0, %1;" : "=f"(r) : "f"(x)); return r;
}
__device__ __forceinline__ float fast_ex2(float x) {
    float r; asm("ex2.approx.f32 %0, %1;" : "=f"(r) : "f"(x)); return r;
}

__global__ __launch_bounds__(256, 4)
void emd_rows_kernel(const float* __restrict__ pred, const float* __restrict__ gt)
{
    __shared__ float sgx[NPTS];
    __shared__ float sgy[NPTS];
    __shared__ float sgz[NPTS];

    const int b    = blockIdx.x / BLOCKS_PER_BATCH;
    const int row0 = (blockIdx.x % BLOCKS_PER_BATCH) * ROWS_PER_BLOCK;

    // Stage this batch's gt points into smem (SoA)
    const float* g = gt + (size_t)b * NPTS * 3;
    for (int i = threadIdx.x; i < NPTS; i += blockDim.x) {
        sgx[i] = g[3 * i + 0];
        sgy[i] = g[3 * i + 1];
        sgz[i] = g[3 * i + 2];
    }
    __syncthreads();

    const int warp = threadIdx.x >> 5;
    const int lane = threadIdx.x & 31;
    const int m0   = row0 + warp * RPW;

    // Per-row constants: qx = -2*px etc., p2 = |p|^2
    float qx[RPW], qy[RPW], qz[RPW], p2[RPW], s[RPW], w[RPW];
    const float* p = pred + ((size_t)b * M + m0) * 3;
#pragma unroll
    for (int r = 0; r < RPW; r++) {
        float px = __ldg(p + 3 * r + 0);
        float py = __ldg(p + 3 * r + 1);
        float pz = __ldg(p + 3 * r + 2);
        qx[r] = -2.0f * px;
        qy[r] = -2.0f * py;
        qz[r] = -2.0f * pz;
        p2[r] = fmaf(px, px, fmaf(py, py, pz * pz));
        s[r]  = 0.0f;
        w[r]  = 0.0f;
    }

    // Main loop: lanes stride over gt points; 8 independent row chains for ILP
#pragma unroll 2
    for (int n = lane; n < NPTS; n += 32) {
        const float ax = sgx[n];
        const float ay = sgy[n];
        const float az = sgz[n];
        const float g2 = fmaf(ax, ax, fmaf(ay, ay, az * az));
#pragma unroll
        for (int r = 0; r < RPW; r++) {
            float t  = fmaf(qx[r], ax, fmaf(qy[r], ay, fmaf(qz[r], az, g2)));
            float d2 = fmaxf(p2[r] + t, 0.0f);
            float d  = fast_sqrt(d2);
            float e  = fast_ex2(d * NEG_K);   // exp(-d / 0.1); <= 1, no overflow;
                                              // underflowing terms are negligible
            s[r] += e;
            w[r]  = fmaf(e, d, w[r]);
        }
    }

    // Warp-reduce s and w per row, write w/s
#pragma unroll
    for (int r = 0; r < RPW; r++) {
        float sv = s[r], wv = w[r];
#pragma unroll
        for (int o = 16; o; o >>= 1) {
            sv += __shfl_xor_sync(0xffffffffu, sv, o);
            wv += __shfl_xor_sync(0xffffffffu, wv, o);
        }
        if (lane == 0)
            g_row[(size_t)b * M + m0 + r] = wv / sv;
    }
}

__global__ void emd_reduce_kernel(float* __restrict__ out)
{
    __shared__ float sh[256];
    float acc = 0.0f;
    for (int i = threadIdx.x; i < BATCH * M; i += 256)
        acc += g_row[i];
    sh[threadIdx.x] = acc;
    __syncthreads();
    for (int stride = 128; stride > 0; stride >>= 1) {
        if (threadIdx.x < stride) sh[threadIdx.x] += sh[threadIdx.x + stride];
        __syncthreads();
    }
    if (threadIdx.x == 0)
        out[0] = sh[0] * (1.0f / (float)(BATCH * M));   // LOSS_WEIGHT = 1.0
}

extern "C" void kernel_launch(void* const* d_in, const int* in_sizes, int n_in,
                              void* d_out, int out_size)
{
    const float* pred = (const float*)d_in[0];  // [B, M, 3] fp32
    const float* gt   = (const float*)d_in[1];  // [B, N, 3] fp32
    float* out        = (float*)d_out;          // scalar fp32

    emd_rows_kernel<<<NBLOCKS, 256>>>(pred, gt);
    emd_reduce_kernel<<<1, 256>>>(out);
}

// round 2
// speedup vs baseline: 1.2493x; 1.2493x over previous
#include <cuda_runtime.h>

#define BATCH 8
#define M 4096
#define NPTS 4096
#define NPAIR 4                       // row pairs per warp (f32x2 packed)
#define RPW (2 * NPAIR)               // 8 rows per warp
#define WARPS 8
#define ROWS_PER_BLOCK (RPW * WARPS)          // 64
#define BLOCKS_PER_BATCH (M / ROWS_PER_BLOCK) // 64
#define NBLOCKS (BATCH * BLOCKS_PER_BATCH)    // 512

// Pre-scale both clouds by C = 10 * log2(e): then u = C*d and
// exp(-d/0.1) = exp2(-u). Row result is (sum e*u / sum e) / C.
#define SCALE_C 14.4269504088896340736f
#define INV_C   (1.0f / SCALE_C)

__device__ float g_part[NBLOCKS];     // one partial per block

typedef unsigned long long ull;

__device__ __forceinline__ ull pack2(float lo, float hi) {
    ull r; asm("mov.b64 %0, {%1, %2};" : "=l"(r) : "f"(lo), "f"(hi)); return r;
}
__device__ __forceinline__ void unpack2(ull v, float& lo, float& hi) {
    asm("mov.b64 {%0, %1}, %2;" : "=f"(lo), "=f"(hi) : "l"(v));
}
__device__ __forceinline__ ull fma2(ull a, ull b, ull c) {
    ull r; asm("fma.rn.f32x2 %0, %1, %2, %3;" : "=l"(r) : "l"(a), "l"(b), "l"(c)); return r;
}
__device__ __forceinline__ ull add2(ull a, ull b) {
    ull r; asm("add.rn.f32x2 %0, %1, %2;" : "=l"(r) : "l"(a), "l"(b)); return r;
}
// abs folds into the MUFU input modifier (handles tiny negative d2 from rounding)
__device__ __forceinline__ float fsqrt_abs(float x) {
    float r; asm("sqrt.approx.f32 %0, %1;" : "=f"(r) : "f"(fabsf(x))); return r;
}
// negation folds into the MUFU input modifier
__device__ __forceinline__ float fex2_neg(float x) {
    float r; asm("ex2.approx.f32 %0, %1;" : "=f"(r) : "f"(-x)); return r;
}

__global__ __launch_bounds__(256, 4)
void emd_rows_kernel(const float* __restrict__ pred, const float* __restrict__ gt)
{
    __shared__ float sgx[NPTS];
    __shared__ float sgy[NPTS];
    __shared__ float sgz[NPTS];
    __shared__ float swarp[WARPS];

    const int b    = blockIdx.x / BLOCKS_PER_BATCH;
    const int row0 = (blockIdx.x % BLOCKS_PER_BATCH) * ROWS_PER_BLOCK;

    // Stage this batch's gt points into smem (SoA), pre-scaled by C
    const float* g = gt + (size_t)b * NPTS * 3;
    for (int i = threadIdx.x; i < NPTS; i += blockDim.x) {
        sgx[i] = SCALE_C * g[3 * i + 0];
        sgy[i] = SCALE_C * g[3 * i + 1];
        sgz[i] = SCALE_C * g[3 * i + 2];
    }
    __syncthreads();

    const int warp = threadIdx.x >> 5;
    const int lane = threadIdx.x & 31;
    const int m0   = row0 + warp * RPW;

    // Packed per-pair constants: q = -2*C*p, p2 = |C*p|^2
    ull qx2[NPAIR], qy2[NPAIR], qz2[NPAIR], p22[NPAIR], s2[NPAIR], w2[NPAIR];
    const float* p = pred + ((size_t)b * M + m0) * 3;
#pragma unroll
    for (int r = 0; r < NPAIR; r++) {
        float pxa = SCALE_C * __ldg(p + 6 * r + 0);
        float pya = SCALE_C * __ldg(p + 6 * r + 1);
        float pza = SCALE_C * __ldg(p + 6 * r + 2);
        float pxb = SCALE_C * __ldg(p + 6 * r + 3);
        float pyb = SCALE_C * __ldg(p + 6 * r + 4);
        float pzb = SCALE_C * __ldg(p + 6 * r + 5);
        qx2[r] = pack2(-2.0f * pxa, -2.0f * pxb);
        qy2[r] = pack2(-2.0f * pya, -2.0f * pyb);
        qz2[r] = pack2(-2.0f * pza, -2.0f * pzb);
        p22[r] = pack2(fmaf(pxa, pxa, fmaf(pya, pya, pza * pza)),
                       fmaf(pxb, pxb, fmaf(pyb, pyb, pzb * pzb)));
        s2[r] = pack2(0.0f, 0.0f);
        w2[r] = pack2(0.0f, 0.0f);
    }

    // Main loop: lanes stride over gt points; 4 packed row-pair chains for ILP
#pragma unroll 2
    for (int n = lane; n < NPTS; n += 32) {
        const float ax = sgx[n];
        const float ay = sgy[n];
        const float az = sgz[n];
        const float g2 = fmaf(ax, ax, fmaf(ay, ay, az * az));
        const ull axx = pack2(ax, ax);
        const ull ayy = pack2(ay, ay);
        const ull azz = pack2(az, az);
        const ull g22 = pack2(g2, g2);
#pragma unroll
        for (int r = 0; r < NPAIR; r++) {
            ull t = fma2(qz2[r], azz, g22);
            t = fma2(qy2[r], ayy, t);
            t = fma2(qx2[r], axx, t);
            t = add2(t, p22[r]);              // packed u^2 = (C*d)^2
            float u2lo, u2hi; unpack2(t, u2lo, u2hi);
            float ulo = fsqrt_abs(u2lo);      // u = C*d
            float uhi = fsqrt_abs(u2hi);
            float elo = fex2_neg(ulo);        // e = exp2(-u) = exp(-d/0.1)
            float ehi = fex2_neg(uhi);
            ull uu = pack2(ulo, uhi);
            ull ee = pack2(elo, ehi);
            s2[r] = add2(s2[r], ee);
            w2[r] = fma2(ee, uu, w2[r]);
        }
    }

    // Warp-reduce each row, lane0 accumulates sum of (w/s) over its 8 rows
    float rowacc = 0.0f;
#pragma unroll
    for (int r = 0; r < NPAIR; r++) {
        float sa, sb, wa, wb;
        unpack2(s2[r], sa, sb);
        unpack2(w2[r], wa, wb);
#pragma unroll
        for (int o = 16; o; o >>= 1) {
            sa += __shfl_xor_sync(0xffffffffu, sa, o);
            sb += __shfl_xor_sync(0xffffffffu, sb, o);
            wa += __shfl_xor_sync(0xffffffffu, wa, o);
            wb += __shfl_xor_sync(0xffffffffu, wb, o);
        }
        if (lane == 0)
            rowacc += wa / sa + wb / sb;
    }
    if (lane == 0)
        swarp[warp] = rowacc * INV_C;
    __syncthreads();

    if (warp == 0) {
        float v = (lane < WARPS) ? swarp[lane] : 0.0f;
#pragma unroll
        for (int o = 16; o; o >>= 1)
            v += __shfl_xor_sync(0xffffffffu, v, o);
        if (lane == 0)
            g_part[blockIdx.x] = v;
    }
}

__global__ void emd_reduce_kernel(float* __restrict__ out)
{
    __shared__ float sh[NBLOCKS];
    float v = g_part[threadIdx.x];            // 512 threads, 1 load each
    sh[threadIdx.x] = v;
    __syncthreads();
    for (int stride = NBLOCKS / 2; stride > 0; stride >>= 1) {
        if (threadIdx.x < stride) sh[threadIdx.x] += sh[threadIdx.x + stride];
        __syncthreads();
    }
    if (threadIdx.x == 0)
        out[0] = sh[0] * (1.0f / (float)(BATCH * M));   // LOSS_WEIGHT = 1.0
}

extern "C" void kernel_launch(void* const* d_in, const int* in_sizes, int n_in,
                              void* d_out, int out_size)
{
    const float* pred = (const float*)d_in[0];  // [B, M, 3] fp32
    const float* gt   = (const float*)d_in[1];  // [B, N, 3] fp32
    float* out        = (float*)d_out;          // scalar fp32

    emd_rows_kernel<<<NBLOCKS, 256>>>(pred, gt);
    emd_reduce_kernel<<<1, NBLOCKS>>>(out);
}

// round 3
// speedup vs baseline: 1.4693x; 1.1761x over previous
#include <cuda_runtime.h>

#define BATCH 8
#define M 4096
#define NPTS 4096
#define NPAIR 2                       // row pairs per warp (f32x2 packed)
#define RPW (2 * NPAIR)               // 4 rows per warp
#define WARPS 8
#define ROWS_PER_BLOCK (RPW * WARPS)          // 32
#define BLOCKS_PER_BATCH (M / ROWS_PER_BLOCK) // 128
#define NBLOCKS (BATCH * BLOCKS_PER_BATCH)    // 1024

// Pre-scale both clouds by C = 10 * log2(e): then u = C*d and
// exp(-d/0.1) = exp2(-u). Row result is (sum e*u / sum e) / C.
#define SCALE_C 14.4269504088896340736f
#define INV_C   (1.0f / SCALE_C)

__device__ float g_part[NBLOCKS];     // one partial per block

typedef unsigned long long ull;

__device__ __forceinline__ ull pack2(float lo, float hi) {
    ull r; asm("mov.b64 %0, {%1, %2};" : "=l"(r) : "f"(lo), "f"(hi)); return r;
}
__device__ __forceinline__ void unpack2(ull v, float& lo, float& hi) {
    asm("mov.b64 {%0, %1}, %2;" : "=f"(lo), "=f"(hi) : "l"(v));
}
__device__ __forceinline__ ull fma2(ull a, ull b, ull c) {
    ull r; asm("fma.rn.f32x2 %0, %1, %2, %3;" : "=l"(r) : "l"(a), "l"(b), "l"(c)); return r;
}
__device__ __forceinline__ ull add2(ull a, ull b) {
    ull r; asm("add.rn.f32x2 %0, %1, %2;" : "=l"(r) : "l"(a), "l"(b)); return r;
}
// abs folds into the MUFU input modifier (handles tiny negative d2 from rounding)
__device__ __forceinline__ float fsqrt_abs(float x) {
    float r; asm("sqrt.approx.f32 %0, %1;" : "=f"(r) : "f"(fabsf(x))); return r;
}
// negation folds into the MUFU input modifier
__device__ __forceinline__ float fex2_neg(float x) {
    float r; asm("ex2.approx.f32 %0, %1;" : "=f"(r) : "f"(-x)); return r;
}

__global__ __launch_bounds__(256, 4)
void emd_rows_kernel(const float* __restrict__ pred, const float* __restrict__ gt)
{
    __shared__ float sgx[NPTS];
    __shared__ float sgy[NPTS];
    __shared__ float sgz[NPTS];
    __shared__ float swarp[WARPS];

    const int b    = blockIdx.x / BLOCKS_PER_BATCH;
    const int row0 = (blockIdx.x % BLOCKS_PER_BATCH) * ROWS_PER_BLOCK;

    // Stage this batch's gt points into smem (SoA), pre-scaled by C
    const float* g = gt + (size_t)b * NPTS * 3;
    for (int i = threadIdx.x; i < NPTS; i += blockDim.x) {
        sgx[i] = SCALE_C * g[3 * i + 0];
        sgy[i] = SCALE_C * g[3 * i + 1];
        sgz[i] = SCALE_C * g[3 * i + 2];
    }
    __syncthreads();

    const int warp = threadIdx.x >> 5;
    const int lane = threadIdx.x & 31;
    const int m0   = row0 + warp * RPW;

    // Packed per-pair constants: q = -2*C*p, p2 = |C*p|^2
    ull qx2[NPAIR], qy2[NPAIR], qz2[NPAIR], p22[NPAIR], s2[NPAIR], w2[NPAIR];
    const float* p = pred + ((size_t)b * M + m0) * 3;
#pragma unroll
    for (int r = 0; r < NPAIR; r++) {
        float pxa = SCALE_C * __ldg(p + 6 * r + 0);
        float pya = SCALE_C * __ldg(p + 6 * r + 1);
        float pza = SCALE_C * __ldg(p + 6 * r + 2);
        float pxb = SCALE_C * __ldg(p + 6 * r + 3);
        float pyb = SCALE_C * __ldg(p + 6 * r + 4);
        float pzb = SCALE_C * __ldg(p + 6 * r + 5);
        qx2[r] = pack2(-2.0f * pxa, -2.0f * pxb);
        qy2[r] = pack2(-2.0f * pya, -2.0f * pyb);
        qz2[r] = pack2(-2.0f * pza, -2.0f * pzb);
        p22[r] = pack2(fmaf(pxa, pxa, fmaf(pya, pya, pza * pza)),
                       fmaf(pxb, pxb, fmaf(pyb, pyb, pzb * pzb)));
        s2[r] = pack2(0.0f, 0.0f);
        w2[r] = pack2(0.0f, 0.0f);
    }

    // Main loop: lanes stride over gt points; 2 packed row-pair chains,
    // unroll 4 for MUFU-latency-covering ILP (8 independent sqrt chains)
#pragma unroll 4
    for (int n = lane; n < NPTS; n += 32) {
        const float ax = sgx[n];
        const float ay = sgy[n];
        const float az = sgz[n];
        const float g2 = fmaf(ax, ax, fmaf(ay, ay, az * az));
        const ull axx = pack2(ax, ax);
        const ull ayy = pack2(ay, ay);
        const ull azz = pack2(az, az);
        const ull g22 = pack2(g2, g2);
#pragma unroll
        for (int r = 0; r < NPAIR; r++) {
            ull t = fma2(qz2[r], azz, g22);
            t = fma2(qy2[r], ayy, t);
            t = fma2(qx2[r], axx, t);
            t = add2(t, p22[r]);              // packed u^2 = (C*d)^2
            float u2lo, u2hi; unpack2(t, u2lo, u2hi);
            float ulo = fsqrt_abs(u2lo);      // u = C*d
            float uhi = fsqrt_abs(u2hi);
            float elo = fex2_neg(ulo);        // e = exp2(-u) = exp(-d/0.1)
            float ehi = fex2_neg(uhi);
            ull uu = pack2(ulo, uhi);
            ull ee = pack2(elo, ehi);
            s2[r] = add2(s2[r], ee);
            w2[r] = fma2(ee, uu, w2[r]);
        }
    }

    // Warp-reduce each row, lane0 accumulates sum of (w/s) over its rows
    float rowacc = 0.0f;
#pragma unroll
    for (int r = 0; r < NPAIR; r++) {
        float sa, sb, wa, wb;
        unpack2(s2[r], sa, sb);
        unpack2(w2[r], wa, wb);
#pragma unroll
        for (int o = 16; o; o >>= 1) {
            sa += __shfl_xor_sync(0xffffffffu, sa, o);
            sb += __shfl_xor_sync(0xffffffffu, sb, o);
            wa += __shfl_xor_sync(0xffffffffu, wa, o);
            wb += __shfl_xor_sync(0xffffffffu, wb, o);
        }
        if (lane == 0)
            rowacc += wa / sa + wb / sb;
    }
    if (lane == 0)
        swarp[warp] = rowacc * INV_C;
    __syncthreads();

    if (warp == 0) {
        float v = (lane < WARPS) ? swarp[lane] : 0.0f;
#pragma unroll
        for (int o = 16; o; o >>= 1)
            v += __shfl_xor_sync(0xffffffffu, v, o);
        if (lane == 0)
            g_part[blockIdx.x] = v;
    }
}

__global__ void emd_reduce_kernel(float* __restrict__ out)
{
    __shared__ float sh[512];
    float acc = 0.0f;
    for (int i = threadIdx.x; i < NBLOCKS; i += 512)
        acc += g_part[i];
    sh[threadIdx.x] = acc;
    __syncthreads();
    for (int stride = 256; stride > 0; stride >>= 1) {
        if (threadIdx.x < stride) sh[threadIdx.x] += sh[threadIdx.x + stride];
        __syncthreads();
    }
    if (threadIdx.x == 0)
        out[0] = sh[0] * (1.0f / (float)(BATCH * M));   // LOSS_WEIGHT = 1.0
}

extern "C" void kernel_launch(void* const* d_in, const int* in_sizes, int n_in,
                              void* d_out, int out_size)
{
    const float* pred = (const float*)d_in[0];  // [B, M, 3] fp32
    const float* gt   = (const float*)d_in[1];  // [B, N, 3] fp32
    float* out        = (float*)d_out;          // scalar fp32

    emd_rows_kernel<<<NBLOCKS, 256>>>(pred, gt);
    emd_reduce_kernel<<<1, 512>>>(out);
}

// round 4
// speedup vs baseline: 1.6034x; 1.0913x over previous
#include <cuda_runtime.h>
#include <cuda_fp16.h>

#define BATCH 8
#define M 4096
#define NPTS 4096
#define ROWS_PER_BLOCK 4
#define NPAIR 2                                  // 2 packed row-pairs = 4 rows
#define BLOCKS_PER_BATCH (M / ROWS_PER_BLOCK)    // 1024
#define NBLOCKS (BATCH * BLOCKS_PER_BATCH)       // 8192
#define WARPS 8
#define SLICE (NPTS / WARPS)                     // 512 gt points per warp
#define GROUPS (SLICE / 128)                     // 4 super-iters (4 pts/lane each)

// f16-exact scale constant: round_to_f16(10*log2(e)) = 14.4296875.
// ex2 argument: 12 - C*d  =>  e' = 2^12 * exp(-d/0.1)^(C/C_true).
// +12 offset keeps e' in f16 range for d up to ~2.5 (worst NN dist << that).
// s and w both carry the 2^12 factor -> cancels in w/s. w accumulates raw d.
#define C_F16 14.4296875f

__device__ float g_part[NBLOCKS];

typedef unsigned long long ull;

__device__ __forceinline__ ull pack2(float lo, float hi) {
    ull r; asm("mov.b64 %0, {%1, %2};" : "=l"(r) : "f"(lo), "f"(hi)); return r;
}
__device__ __forceinline__ void unpack2(ull v, float& lo, float& hi) {
    asm("mov.b64 {%0, %1}, %2;" : "=f"(lo), "=f"(hi) : "l"(v));
}
__device__ __forceinline__ ull fma2(ull a, ull b, ull c) {
    ull r; asm("fma.rn.f32x2 %0, %1, %2, %3;" : "=l"(r) : "l"(a), "l"(b), "l"(c)); return r;
}
__device__ __forceinline__ ull add2(ull a, ull b) {
    ull r; asm("add.rn.f32x2 %0, %1, %2;" : "=l"(r) : "l"(a), "l"(b)); return r;
}
__device__ __forceinline__ float fsqrt_abs(float x) {
    float r; asm("sqrt.approx.f32 %0, %1;" : "=f"(r) : "f"(fabsf(x))); return r;
}
__device__ __forceinline__ __half2 ex2_h2(__half2 x) {
    unsigned xi = reinterpret_cast<unsigned&>(x), ri;
    asm("ex2.approx.f16x2 %0, %1;" : "=r"(ri) : "r"(xi));
    return reinterpret_cast<__half2&>(ri);
}

__global__ __launch_bounds__(256, 4)
void emd_rows_kernel(const float* __restrict__ pred, const float* __restrict__ gt)
{
    __shared__ float sS[WARPS][ROWS_PER_BLOCK];
    __shared__ float sW[WARPS][ROWS_PER_BLOCK];

    const int b    = blockIdx.x / BLOCKS_PER_BATCH;
    const int m0   = (blockIdx.x % BLOCKS_PER_BATCH) * ROWS_PER_BLOCK;
    const int warp = threadIdx.x >> 5;
    const int lane = threadIdx.x & 31;

    // Per-pair constants (raw, unscaled): q = -2p, p2 = |p|^2
    ull qx2[NPAIR], qy2[NPAIR], qz2[NPAIR], p22[NPAIR], s2[NPAIR], w2[NPAIR];
    const float* p = pred + ((size_t)b * M + m0) * 3;
#pragma unroll
    for (int r = 0; r < NPAIR; r++) {
        float pxa = __ldg(p + 6 * r + 0);
        float pya = __ldg(p + 6 * r + 1);
        float pza = __ldg(p + 6 * r + 2);
        float pxb = __ldg(p + 6 * r + 3);
        float pyb = __ldg(p + 6 * r + 4);
        float pzb = __ldg(p + 6 * r + 5);
        qx2[r] = pack2(-2.0f * pxa, -2.0f * pxb);
        qy2[r] = pack2(-2.0f * pya, -2.0f * pyb);
        qz2[r] = pack2(-2.0f * pza, -2.0f * pzb);
        p22[r] = pack2(fmaf(pxa, pxa, fmaf(pya, pya, pza * pza)),
                       fmaf(pxb, pxb, fmaf(pyb, pyb, pzb * pzb)));
        s2[r] = pack2(0.0f, 0.0f);
        w2[r] = pack2(0.0f, 0.0f);
    }

    const __half2 hCneg = __floats2half2_rn(-C_F16, -C_F16);  // exact in f16
    const __half2 h12   = __floats2half2_rn(12.0f, 12.0f);

    // Each warp streams its disjoint 512-pt gt slice straight from L2 via
    // LDG.128; lane handles 4 consecutive points per group (order change in
    // the sums is deterministic).
    const float4* g4 = (const float4*)(gt) + (size_t)b * (NPTS * 3 / 4)
                     + warp * (SLICE * 3 / 4) + 3 * lane;

#pragma unroll
    for (int gi = 0; gi < GROUPS; gi++) {
        const float4 v0 = g4[gi * 96 + 0];
        const float4 v1 = g4[gi * 96 + 1];
        const float4 v2 = g4[gi * 96 + 2];
        float px[4], py[4], pz[4];
        px[0] = v0.x; py[0] = v0.y; pz[0] = v0.z;
        px[1] = v0.w; py[1] = v1.x; pz[1] = v1.y;
        px[2] = v1.z; py[2] = v1.w; pz[2] = v2.x;
        px[3] = v2.y; py[3] = v2.z; pz[3] = v2.w;
#pragma unroll
        for (int k = 0; k < 4; k++) {
            const float ax = px[k], ay = py[k], az = pz[k];
            const float gg = fmaf(ax, ax, fmaf(ay, ay, az * az));
            const ull axx = pack2(ax, ax);
            const ull ayy = pack2(ay, ay);
            const ull azz = pack2(az, az);
            const ull g22 = pack2(gg, gg);
#pragma unroll
            for (int r = 0; r < NPAIR; r++) {
                ull t = add2(g22, p22[r]);
                t = fma2(qz2[r], azz, t);
                t = fma2(qy2[r], ayy, t);
                t = fma2(qx2[r], axx, t);          // packed d^2
                float d2lo, d2hi; unpack2(t, d2lo, d2hi);
                float dlo = fsqrt_abs(d2lo);
                float dhi = fsqrt_abs(d2hi);
                __half2 hd  = __floats2half2_rn(dlo, dhi);
                __half2 arg = __hfma2(hd, hCneg, h12);   // 12 - C*d
                __half2 e2  = ex2_h2(arg);               // 2^12 * softmin weight
                float elo = __low2float(e2);
                float ehi = __high2float(e2);
                ull ee = pack2(elo, ehi);
                s2[r] = add2(s2[r], ee);
                w2[r] = fma2(ee, pack2(dlo, dhi), w2[r]);
            }
        }
    }

    // Warp-reduce the 4 rows' (s, w), stash per-warp partials
    float sv[4], wv[4];
    unpack2(s2[0], sv[0], sv[1]); unpack2(s2[1], sv[2], sv[3]);
    unpack2(w2[0], wv[0], wv[1]); unpack2(w2[1], wv[2], wv[3]);
#pragma unroll
    for (int r = 0; r < 4; r++) {
#pragma unroll
        for (int o = 16; o; o >>= 1) {
            sv[r] += __shfl_xor_sync(0xffffffffu, sv[r], o);
            wv[r] += __shfl_xor_sync(0xffffffffu, wv[r], o);
        }
    }
    if (lane == 0) {
#pragma unroll
        for (int r = 0; r < 4; r++) { sS[warp][r] = sv[r]; sW[warp][r] = wv[r]; }
    }
    __syncthreads();

    // Warp 0 combines 8 warp-partials per row, sums the 4 rows' w/s
    if (warp == 0) {
        const int row = lane & 3;
        const int wi  = lane >> 2;
        float s = sS[wi][row];
        float w = sW[wi][row];
#pragma unroll
        for (int o = 4; o < 32; o <<= 1) {
            s += __shfl_xor_sync(0xffffffffu, s, o);
            w += __shfl_xor_sync(0xffffffffu, w, o);
        }
        float val = (wi == 0) ? __fdividef(w, s) : 0.0f;
        val += __shfl_xor_sync(0xffffffffu, val, 1);
        val += __shfl_xor_sync(0xffffffffu, val, 2);
        if (lane == 0)
            g_part[blockIdx.x] = val;
    }
}

__global__ void emd_reduce_kernel(float* __restrict__ out)
{
    __shared__ float sh[32];
    const int t = threadIdx.x;          // 1024 threads
    float acc = 0.0f;
#pragma unroll
    for (int i = t; i < NBLOCKS; i += 1024)
        acc += g_part[i];
#pragma unroll
    for (int o = 16; o; o >>= 1)
        acc += __shfl_xor_sync(0xffffffffu, acc, o);
    if ((t & 31) == 0) sh[t >> 5] = acc;
    __syncthreads();
    if (t < 32) {
        float v = sh[t];
#pragma unroll
        for (int o = 16; o; o >>= 1)
            v += __shfl_xor_sync(0xffffffffu, v, o);
        if (t == 0)
            out[0] = v * (1.0f / (float)(BATCH * M));   // LOSS_WEIGHT = 1.0
    }
}

extern "C" void kernel_launch(void* const* d_in, const int* in_sizes, int n_in,
                              void* d_out, int out_size)
{
    const float* pred = (const float*)d_in[0];  // [B, M, 3] fp32
    const float* gt   = (const float*)d_in[1];  // [B, N, 3] fp32
    float* out        = (float*)d_out;          // scalar fp32

    emd_rows_kernel<<<NBLOCKS, 256>>>(pred, gt);
    emd_reduce_kernel<<<1, 1024>>>(out);
}